// round 15
// baseline (speedup 1.0000x reference)
#include <cuda_runtime.h>

#define N_CODES 4096
#define N_EDGES 8192
#define EMB     128
#define KDIM    512
#define NNZ     65536
#define NTOT    33554432
#define KSEL    6553
#define BAND_CAP 24576
#define SEL_CAP  8192

__device__ float    g_eX[N_EDGES * EMB];
__device__ int      g_icnt[N_EDGES];
__device__ float    g_A[N_CODES * KDIM];
__device__ float    g_B[N_EDGES * KDIM];
// fragment-major bf16-pair operand buffers (see build_k for the layout)
__device__ unsigned g_Ahp[N_CODES * 256];
__device__ unsigned g_Bhp[N_EDGES * 256];
__device__ unsigned g_S16[NTOT / 2];        // S matrix, packed bf16 pairs
__device__ unsigned g_mbit[NTOT / 32];      // mask bitmap (existing incidences)
__device__ int      g_h1[4096];
__device__ unsigned g_sel[SEL_CAP];
__device__ unsigned g_band[BAND_CAP];
__device__ unsigned long long g_bkey[BAND_CAP];
__device__ int      g_sel_n, g_band_n;
__device__ float    g_tlo, g_thi;

__device__ __forceinline__ unsigned mkey(float f) {
    unsigned u = __float_as_uint(f);
    return (u & 0x80000000u) ? ~u : (u | 0x80000000u);
}
__device__ __forceinline__ float key2f(unsigned k) {
    unsigned u = (k & 0x80000000u) ? (k ^ 0x80000000u) : ~k;
    return __uint_as_float(u);
}
__device__ __forceinline__ unsigned short f2bf(float x) {
    unsigned u = __float_as_uint(x);
    return (unsigned short)((u + 0x7fffu + ((u >> 16) & 1u)) >> 16);
}
__device__ __forceinline__ float bf2f(unsigned short h) {
    return __uint_as_float(((unsigned)h) << 16);
}

// ---------------- launch 0: zero scratch ----------------
__global__ void zero_k() {
    int i = blockIdx.x * blockDim.x + threadIdx.x, st = gridDim.x * blockDim.x;
    for (int j = i; j < 4096; j += st) g_h1[j] = 0;
    for (int j = i; j < NTOT / 32; j += st) g_mbit[j] = 0;
    for (int j = i; j < N_EDGES * EMB; j += st) g_eX[j] = 0.f;
    for (int j = i; j < N_EDGES; j += st) g_icnt[j] = 0;
    if (i == 0) { g_sel_n = 0; g_band_n = 0; }
}

// ---------------- launch 1: fused edge counts + sums ----------------
__global__ void edgecnt_k(const float* __restrict__ X, const int* __restrict__ V,
                          const int* __restrict__ E) {
    int i = blockIdx.x * blockDim.x + threadIdx.x;
    int nz = i >> 5, lane = i & 31;
    if (nz >= NNZ) return;
    int e = E[nz];
    if (lane == 0) atomicAdd(&g_icnt[e], 1);
    float4 x = ((const float4*)(X + V[nz] * EMB))[lane];
    float* d = g_eX + e * EMB + lane * 4;
    atomicAdd(d + 0, x.x); atomicAdd(d + 1, x.y);
    atomicAdd(d + 2, x.z); atomicAdd(d + 3, x.w);
}

// ---------------- launch 2: build normalized operands ----------------
// A layout: uint index = ((rb*16 + c)*16 + (mblk*2+ks))*128 + dlane*4 + q
//   rb=row>>7, mblk=(row&127)>>4, rsub=row&15, c=pair>>4, ks=(pair&15)>>3,
//   kq=pair&7, dlane=((rsub&7)<<2)|(kq&3), q=((kq>>2)<<1)|(rsub>>3)
//   -> per-lane uint4 = mma a0..a3: (r,kp),(r+8,kp),(r,kp+4),(r+8,kp+4)
// B layout: uint index = ((rb*16 + c)*32 + (nblk*2+ks))*64 + dlane*2 + q
//   nblk=(col&127)>>3, csub=col&7, dlane=(csub<<2)|(kq&3), q=kq>>2
//   -> per-lane uint2 = mma b0,b1
__global__ void build_k(const float* __restrict__ X, const float* __restrict__ W) {
    int gw = (blockIdx.x * blockDim.x + threadIdx.x) >> 5, lane = threadIdx.x & 31;
    if (gw >= (N_CODES + N_EDGES) * 4) return;
    int h = gw & 3, r = gw >> 2;
    float4 wv = ((const float4*)(W + h * EMB))[lane];
    float4 t;
    if (r < N_CODES) {
        float4 x = ((const float4*)(X + r * EMB))[lane];
        t.x = x.x * wv.x; t.y = x.y * wv.y; t.z = x.z * wv.z; t.w = x.w * wv.w;
    } else {
        int m = r - N_CODES;
        float inv = 1.0f / fmaxf((float)g_icnt[m], 1.0f);
        float4 s = ((const float4*)(g_eX + m * EMB))[lane];
        t.x = s.x * inv * wv.x; t.y = s.y * inv * wv.y;
        t.z = s.z * inv * wv.z; t.w = s.w * inv * wv.w;
    }
    float ss = t.x * t.x + t.y * t.y + t.z * t.z + t.w * t.w;
#pragma unroll
    for (int o = 16; o; o >>= 1) ss += __shfl_xor_sync(0xffffffffu, ss, o);
    float dn = 1.0f / fmaxf(sqrtf(ss), 1e-6f);
    float4 ov = make_float4(t.x * dn, t.y * dn, t.z * dn, t.w * dn);
    bool isA = (r < N_CODES);
    int rl = isA ? r : (r - N_CODES);
    float* dst = isA ? (g_A + (size_t)rl * KDIM + h * EMB)
                     : (g_B + (size_t)rl * KDIM + h * EMB);
    ((float4*)dst)[lane] = ov;
    unsigned short h0 = f2bf(ov.x), h1 = f2bf(ov.y), h2 = f2bf(ov.z), h3 = f2bf(ov.w);
    unsigned v0 = (unsigned)h0 | ((unsigned)h1 << 16);
    unsigned v1 = (unsigned)h2 | ((unsigned)h3 << 16);
    // pair indices p0 = h*64 + lane*2 (v0), p0+1 (v1)
    int p0 = h * 64 + lane * 2;
    int c  = p0 >> 4;
    int w  = p0 & 15;
    int ks = w >> 3;
    int kq = w & 7;                      // even
    int rb = rl >> 7, rr = rl & 127;
    if (isA) {
        int sub = ((rr >> 4) * 2 + ks);
        int rsub = rr & 15;
        int dlane = ((rsub & 7) << 2) | (kq & 3);
        int q = ((kq >> 2) << 1) | (rsub >> 3);
        int base = ((rb * 16 + c) * 16 + sub) * 128;
        g_Ahp[base + dlane * 4 + q] = v0;
        g_Ahp[base + (dlane + 1) * 4 + q] = v1;
    } else {
        int sub = ((rr >> 3) * 2 + ks);
        int csub = rr & 7;
        int dlane = (csub << 2) | (kq & 3);
        int q = kq >> 2;
        int base = ((rb * 16 + c) * 32 + sub) * 64;
        g_Bhp[base + dlane * 2 + q] = v0;
        g_Bhp[base + (dlane + 1) * 2 + q] = v1;
    }
}

// ---------------- launch 3: smem-free bf16 GEMM + hist + d_out zero ---------------
__device__ __forceinline__ void mma16(float* d, const unsigned* a, const unsigned* b) {
    asm volatile("mma.sync.aligned.m16n8k16.row.col.f32.bf16.bf16.f32 "
        "{%0,%1,%2,%3}, {%4,%5,%6,%7}, {%8,%9}, {%0,%1,%2,%3};\n"
        : "+f"(d[0]), "+f"(d[1]), "+f"(d[2]), "+f"(d[3])
        : "r"(a[0]), "r"(a[1]), "r"(a[2]), "r"(a[3]), "r"(b[0]), "r"(b[1]));
}

__global__ void __launch_bounds__(512, 2) gemm_k(float* __restrict__ S) {
    __shared__ int hsm[4096];
    const int tid = threadIdx.x, lane = tid & 31, wid = tid >> 5;
    const int wm = wid & 3, wn = wid >> 2;
    const int bx = blockIdx.x, by = blockIdx.y;

    float acc[2][4][4];
#pragma unroll
    for (int i = 0; i < 2; i++)
#pragma unroll
        for (int j = 0; j < 4; j++)
#pragma unroll
            for (int q = 0; q < 4; q++) acc[i][j][q] = 0.f;

    for (int c = 0; c < 16; c++) {
        uint4 ahv[2][2];
#pragma unroll
        for (int mt = 0; mt < 2; mt++)
#pragma unroll
            for (int ks = 0; ks < 2; ks++) {
                int sub = (wm * 2 + mt) * 2 + ks;
                ahv[mt][ks] = *(const uint4*)&g_Ahp[(size_t)(((by * 16 + c) * 16 + sub)) * 128 + lane * 4];
            }
        uint2 bhv[4][2];
#pragma unroll
        for (int nt = 0; nt < 4; nt++)
#pragma unroll
            for (int ks = 0; ks < 2; ks++) {
                int sub = (wn * 4 + nt) * 2 + ks;
                bhv[nt][ks] = *(const uint2*)&g_Bhp[(size_t)(((bx * 16 + c) * 32 + sub)) * 64 + lane * 2];
            }
#pragma unroll
        for (int ks = 0; ks < 2; ks++)
#pragma unroll
            for (int mt = 0; mt < 2; mt++)
#pragma unroll
                for (int nt = 0; nt < 4; nt++)
                    mma16(acc[mt][nt], (const unsigned*)&ahv[mt][ks],
                          (const unsigned*)&bhv[nt][ks]);
        __syncthreads();   // keep warps in lockstep for L1 tile locality
    }

    // epilogue: scale, round to bf16, store pairs, zero d_out, 12-bit histogram
    for (int j = tid; j < 4096; j += 512) hsm[j] = 0;
    __syncthreads();
    float2 zz = make_float2(0.f, 0.f);
#pragma unroll
    for (int mt = 0; mt < 2; mt++) {
        int rg = (by << 7) + (wm << 5) + (mt << 4) + (lane >> 2);
#pragma unroll
        for (int nt = 0; nt < 4; nt++) {
            int cg = (bx << 7) + (wn << 5) + (nt << 3) + ((lane & 3) << 1);
            unsigned short b0 = f2bf(acc[mt][nt][0] * 0.25f);
            unsigned short b1 = f2bf(acc[mt][nt][1] * 0.25f);
            unsigned short b2 = f2bf(acc[mt][nt][2] * 0.25f);
            unsigned short b3 = f2bf(acc[mt][nt][3] * 0.25f);
            g_S16[((size_t)rg * N_EDGES + cg) >> 1] = (unsigned)b0 | ((unsigned)b1 << 16);
            g_S16[((size_t)(rg + 8) * N_EDGES + cg) >> 1] = (unsigned)b2 | ((unsigned)b3 << 16);
            *(float2*)(S + (size_t)rg * N_EDGES + cg) = zz;
            *(float2*)(S + (size_t)(rg + 8) * N_EDGES + cg) = zz;
            atomicAdd(&hsm[mkey(bf2f(b0)) >> 20], 1);
            atomicAdd(&hsm[mkey(bf2f(b1)) >> 20], 1);
            atomicAdd(&hsm[mkey(bf2f(b2)) >> 20], 1);
            atomicAdd(&hsm[mkey(bf2f(b3)) >> 20], 1);
        }
    }
    __syncthreads();
    for (int j = tid; j < 4096; j += 512) {
        int v = hsm[j];
        if (v) atomicAdd(&g_h1[j], v);
    }
}

// ---------------- launch 4: mark existing incidences in bitmap + hist fixup -------
__global__ void mask_k(const int* __restrict__ V, const int* __restrict__ E) {
    int i = blockIdx.x * blockDim.x + threadIdx.x;
    if (i >= NNZ) return;
    unsigned idx = (unsigned)V[i] * N_EDGES + (unsigned)E[i];
    unsigned bit = 1u << (idx & 31);
    unsigned old = atomicOr(&g_mbit[idx >> 5], bit);
    if (!(old & bit)) {   // exactly-once per (V,E) duplicate group
        unsigned pr = g_S16[idx >> 1];
        unsigned short hv = (idx & 1) ? (unsigned short)(pr >> 16)
                                      : (unsigned short)(pr & 0xffffu);
        atomicSub(&g_h1[mkey(bf2f(hv)) >> 20], 1);
    }
}

// ---------------- launch 5: pick 12-bit threshold bucket ----------------
__global__ void scan12_k() {
    __shared__ int tot[1024];
    int t = threadIdx.x, base = t * 4;
    int loc[4], s = 0;
#pragma unroll
    for (int j = 0; j < 4; j++) { loc[j] = g_h1[base + j]; s += loc[j]; }
    tot[t] = s; __syncthreads();
    int above = 0;
    for (int u = t + 1; u < 1024; u++) above += tot[u];
    for (int j = 3; j >= 0; j--) {
        int v = loc[j];
        if (above < KSEL && above + v >= KSEL) {
            unsigned klo = (unsigned)(base + j) << 20;
            g_tlo = key2f(klo) - 2.5e-3f;   // hi-only (1e-3) + bf16-S rounding + slack
            g_thi = key2f(klo + 0x100000u) + 2.5e-3f;
        }
        above += v;
    }
}

// ---------------- launch 6: classify candidates (read-only sweep) ----------------
__global__ void collect_k() {
    float tlo = g_tlo, thi = g_thi;
    int i = blockIdx.x * blockDim.x + threadIdx.x, st = gridDim.x * blockDim.x;
    for (; i < NTOT / 8; i += st) {
        uint4 pv = ((const uint4*)g_S16)[i];
        unsigned pw[4] = {pv.x, pv.y, pv.z, pv.w};
#pragma unroll
        for (int j = 0; j < 8; j++) {
            unsigned short hv = (j & 1) ? (unsigned short)(pw[j >> 1] >> 16)
                                        : (unsigned short)(pw[j >> 1] & 0xffffu);
            float f = bf2f(hv);
            if (f > tlo) {
                unsigned idx = (unsigned)(i * 8 + j);
                if (g_mbit[idx >> 5] & (1u << (idx & 31))) continue;  // masked
                if (f > thi) {
                    int p = atomicAdd(&g_sel_n, 1);
                    if (p < SEL_CAP) g_sel[p] = idx;
                } else {
                    int p = atomicAdd(&g_band_n, 1);
                    if (p < BAND_CAP) g_band[p] = idx;
                }
            }
        }
    }
}

// ---------------- launch 7: fp64 recompute of band entries ----------------
__global__ void exactval_k() {
    int nb = g_band_n; if (nb > BAND_CAP) nb = BAND_CAP;
    int j = blockIdx.x * 8 + (threadIdx.x >> 5);
    if (j >= nb) return;
    int lane = threadIdx.x & 31;
    unsigned idx = g_band[j];
    const float* a = g_A + (size_t)(idx >> 13) * KDIM;
    const float* b = g_B + (size_t)(idx & 8191) * KDIM;
    double s = 0.0;
    for (int t = lane; t < KDIM; t += 32) s += (double)a[t] * (double)b[t];
#pragma unroll
    for (int o = 16; o; o >>= 1) s += __shfl_down_sync(0xffffffffu, s, o);
    if (lane == 0) {
        unsigned long long u = (unsigned long long)__double_as_longlong(s * 0.25);
        g_bkey[j] = (u & 0x8000000000000000ull) ? ~u : (u | 0x8000000000000000ull);
    }
}

// ---------------- launch 8: byte-digit radix select (ties -> lowest index) --------
__global__ void bandsel_k() {
    __shared__ int hist[256];
    __shared__ int s_t, s_n;
    __shared__ unsigned long long s_prefix;
    int nb = g_band_n; if (nb > BAND_CAP) nb = BAND_CAP;
    int nsel = g_sel_n; if (nsel > SEL_CAP) nsel = SEL_CAP;
    int t0 = KSEL - nsel;
    int tid = threadIdx.x;
    if (t0 <= 0) { if (tid == 0) g_sel_n = nsel; return; }
    if (t0 >= nb) {
        for (int j = tid; j < nb; j += 1024) g_sel[nsel + j] = g_band[j];
        if (tid == 0) g_sel_n = nsel + nb;
        return;
    }
    if (tid == 0) { s_t = t0; s_prefix = 0ull; }
    __syncthreads();
    for (int b = 7; b >= 0; b--) {
        for (int j = tid; j < 256; j += 1024) hist[j] = 0;
        __syncthreads();
        unsigned long long pref = s_prefix;
        for (int j = tid; j < nb; j += 1024) {
            unsigned long long k = g_bkey[j];
            bool match = (b == 7) || ((k >> ((b + 1) * 8)) == (pref >> ((b + 1) * 8)));
            if (match) atomicAdd(&hist[(int)((k >> (b * 8)) & 255u)], 1);
        }
        __syncthreads();
        if (tid == 0) {
            int t = s_t, above = 0, d;
            for (d = 255; d > 0; d--) {
                if (above + hist[d] >= t) break;
                above += hist[d];
            }
            s_t = t - above;
            s_prefix = pref | ((unsigned long long)(unsigned)d << (b * 8));
        }
        __syncthreads();
    }
    unsigned long long thr = s_prefix;
    if (tid == 0) s_n = nsel;
    __syncthreads();
    for (int j = tid; j < nb; j += 1024)
        if (g_bkey[j] > thr) { int p = atomicAdd(&s_n, 1); g_sel[p] = g_band[j]; }
    __syncthreads();
    if (tid == 0) {
        int need = s_t;
        while (need > 0) {
            unsigned best = 0xFFFFFFFFu; int bj = -1;
            for (int j = 0; j < nb; j++)
                if (g_bkey[j] == thr && g_band[j] < best) { best = g_band[j]; bj = j; }
            if (bj < 0) break;
            g_sel[s_n++] = best; g_bkey[bj] = 0; need--;
        }
        g_sel_n = s_n;
    }
}

// ---------------- threefry mask + scatters ----------------
__device__ __forceinline__ unsigned rotl32(unsigned x, int r) {
    return __funnelshift_l(x, x, r);
}
__device__ __forceinline__ unsigned tf_bits(unsigned c0, unsigned c1) {
    const unsigned k0 = 0u, k1 = 42u, k2 = 0u ^ 42u ^ 0x1BD11BDAu;
    unsigned x0 = c0 + k0, x1 = c1 + k1;
#define TR(a) x0 += x1; x1 = rotl32(x1, a); x1 ^= x0;
    TR(13) TR(15) TR(26) TR(6)   x0 += k1; x1 += k2 + 1u;
    TR(17) TR(29) TR(16) TR(24)  x0 += k2; x1 += k0 + 2u;
    TR(13) TR(15) TR(26) TR(6)   x0 += k0; x1 += k1 + 3u;
    TR(17) TR(29) TR(16) TR(24)  x0 += k1; x1 += k2 + 4u;
    TR(13) TR(15) TR(26) TR(6)   x0 += k2; x1 += k0 + 5u;
#undef TR
    return x0 ^ x1;
}
__device__ __forceinline__ float maskval(unsigned idx, float p) {
    unsigned bits = tf_bits(0u, idx);
    float u01 = __uint_as_float((bits >> 9) | 0x3f800000u) - 1.0f;
    const float MINV = 1e-6f, MAXV = (float)(1.0 - 1e-6);
    float u = fmaxf(MINV, u01 * (MAXV - MINV) + MINV);
    float lg = (logf(p) - log1pf(-p) + logf(u) - log1pf(-u)) * 2.0f;
    return 1.0f / (1.0f + expf(-lg));
}
__global__ void scat_old_k(const int* __restrict__ V, const int* __restrict__ E,
                           const float* __restrict__ P, float* __restrict__ out) {
    int i = blockIdx.x * blockDim.x + threadIdx.x;
    if (i >= NNZ) return;
    unsigned idx = (unsigned)V[i] * N_EDGES + (unsigned)E[i];
    out[idx] = maskval(idx, P[idx]);
}
__global__ void scat_new_k(const float* __restrict__ P, float* __restrict__ out) {
    int i = blockIdx.x * blockDim.x + threadIdx.x;
    if (i >= g_sel_n) return;
    unsigned idx = g_sel[i];
    out[idx] = maskval(idx, P[idx]);
}

// ---------------- launch ----------------
extern "C" void kernel_launch(void* const* d_in, const int* in_sizes, int n_in,
                              void* d_out, int out_size) {
    const float* X = (const float*)d_in[0];
    const int*   V = (const int*)d_in[2];
    const int*   E = (const int*)d_in[3];
    const float* P = (const float*)d_in[4];
    const float* W = (const float*)d_in[5];
    float* S = (float*)d_out;

    zero_k<<<2048, 256>>>();                                     // 0
    edgecnt_k<<<NNZ * 32 / 256, 256>>>(X, V, E);                 // 1
    build_k<<<(N_CODES + N_EDGES) * 4 * 32 / 256, 256>>>(X, W);  // 2
    gemm_k<<<dim3(N_EDGES / 128, N_CODES / 128), 512>>>(S);      // 3  <- profiled slot
    mask_k<<<NNZ / 256, 256>>>(V, E);                            // 4
    scan12_k<<<1, 1024>>>();                                     // 5
    collect_k<<<4096, 256>>>();                                  // 6
    exactval_k<<<(BAND_CAP + 7) / 8, 256>>>();                   // 7
    bandsel_k<<<1, 1024>>>();                                    // 8
    scat_old_k<<<NNZ / 256, 256>>>(V, E, P, S);                  // 9
    scat_new_k<<<32, 256>>>(P, S);                               // 10
}

// round 16
// speedup vs baseline: 1.0204x; 1.0204x over previous
#include <cuda_runtime.h>

#define N_CODES 4096
#define N_EDGES 8192
#define EMB     128
#define KDIM    512
#define NNZ     65536
#define NTOT    33554432
#define KSEL    6553
#define BAND_CAP 24576
#define SEL_CAP  8192

__device__ float    g_eX[N_EDGES * EMB];
__device__ int      g_icnt[N_EDGES];
__device__ float    g_A[N_CODES * KDIM];
__device__ float    g_B[N_EDGES * KDIM];
// bf16 hi operand buffers, pair-major (uint = bf16x2, 2 K-elems)
__device__ unsigned g_Ahp[N_CODES * 256];
__device__ unsigned g_Bhp[N_EDGES * 256];
__device__ unsigned g_S16[NTOT / 2];        // S matrix, packed bf16 pairs
__device__ unsigned g_mbit[NTOT / 32];      // mask bitmap (existing incidences)
__device__ int      g_h1[4096];
__device__ unsigned g_sel[SEL_CAP];
__device__ unsigned g_band[BAND_CAP];
__device__ unsigned long long g_bkey[BAND_CAP];
__device__ int      g_sel_n, g_band_n;
__device__ float    g_tlo, g_thi;

__device__ __forceinline__ unsigned mkey(float f) {
    unsigned u = __float_as_uint(f);
    return (u & 0x80000000u) ? ~u : (u | 0x80000000u);
}
__device__ __forceinline__ float key2f(unsigned k) {
    unsigned u = (k & 0x80000000u) ? (k ^ 0x80000000u) : ~k;
    return __uint_as_float(u);
}
__device__ __forceinline__ unsigned short f2bf(float x) {
    unsigned u = __float_as_uint(x);
    return (unsigned short)((u + 0x7fffu + ((u >> 16) & 1u)) >> 16);
}
__device__ __forceinline__ float bf2f(unsigned short h) {
    return __uint_as_float(((unsigned)h) << 16);
}

// ---------------- launch 0: zero scratch ----------------
__global__ void zero_k() {
    int i = blockIdx.x * blockDim.x + threadIdx.x, st = gridDim.x * blockDim.x;
    for (int j = i; j < 4096; j += st) g_h1[j] = 0;
    for (int j = i; j < NTOT / 32; j += st) g_mbit[j] = 0;
    for (int j = i; j < N_EDGES * EMB; j += st) g_eX[j] = 0.f;
    for (int j = i; j < N_EDGES; j += st) g_icnt[j] = 0;
    if (i == 0) { g_sel_n = 0; g_band_n = 0; }
}

// ---------------- launch 1: fused edge counts + sums ----------------
__global__ void edgecnt_k(const float* __restrict__ X, const int* __restrict__ V,
                          const int* __restrict__ E) {
    int i = blockIdx.x * blockDim.x + threadIdx.x;
    int nz = i >> 5, lane = i & 31;
    if (nz >= NNZ) return;
    int e = E[nz];
    if (lane == 0) atomicAdd(&g_icnt[e], 1);
    float4 x = ((const float4*)(X + V[nz] * EMB))[lane];
    float* d = g_eX + e * EMB + lane * 4;
    atomicAdd(d + 0, x.x); atomicAdd(d + 1, x.y);
    atomicAdd(d + 2, x.z); atomicAdd(d + 3, x.w);
}

// ---------------- launch 2: build normalized operands ----------------
__global__ void build_k(const float* __restrict__ X, const float* __restrict__ W) {
    int gw = (blockIdx.x * blockDim.x + threadIdx.x) >> 5, lane = threadIdx.x & 31;
    if (gw >= (N_CODES + N_EDGES) * 4) return;
    int h = gw & 3, r = gw >> 2;
    float4 wv = ((const float4*)(W + h * EMB))[lane];
    float4 t;
    if (r < N_CODES) {
        float4 x = ((const float4*)(X + r * EMB))[lane];
        t.x = x.x * wv.x; t.y = x.y * wv.y; t.z = x.z * wv.z; t.w = x.w * wv.w;
    } else {
        int m = r - N_CODES;
        float inv = 1.0f / fmaxf((float)g_icnt[m], 1.0f);
        float4 s = ((const float4*)(g_eX + m * EMB))[lane];
        t.x = s.x * inv * wv.x; t.y = s.y * inv * wv.y;
        t.z = s.z * inv * wv.z; t.w = s.w * inv * wv.w;
    }
    float ss = t.x * t.x + t.y * t.y + t.z * t.z + t.w * t.w;
#pragma unroll
    for (int o = 16; o; o >>= 1) ss += __shfl_xor_sync(0xffffffffu, ss, o);
    float dn = 1.0f / fmaxf(sqrtf(ss), 1e-6f);
    float4 ov = make_float4(t.x * dn, t.y * dn, t.z * dn, t.w * dn);
    bool isA = (r < N_CODES);
    int rl = isA ? r : (r - N_CODES);
    float* dst = isA ? (g_A + (size_t)rl * KDIM + h * EMB)
                     : (g_B + (size_t)rl * KDIM + h * EMB);
    ((float4*)dst)[lane] = ov;
    unsigned short h0 = f2bf(ov.x), h1 = f2bf(ov.y), h2 = f2bf(ov.z), h3 = f2bf(ov.w);
    uint2 hv = make_uint2((unsigned)h0 | ((unsigned)h1 << 16),
                          (unsigned)h2 | ((unsigned)h3 << 16));
    size_t po = (size_t)rl * 256 + h * 64 + lane * 2;
    *(uint2*)((isA ? g_Ahp : g_Bhp) + po) = hv;
}

// ---------------- launch 3: bf16 smem GEMM + hist + d_out zero --------------------
__device__ __forceinline__ void mma16(float* d, const unsigned* a, const unsigned* b) {
    asm volatile("mma.sync.aligned.m16n8k16.row.col.f32.bf16.bf16.f32 "
        "{%0,%1,%2,%3}, {%4,%5,%6,%7}, {%8,%9}, {%0,%1,%2,%3};\n"
        : "+f"(d[0]), "+f"(d[1]), "+f"(d[2]), "+f"(d[3])
        : "r"(a[0]), "r"(a[1]), "r"(a[2]), "r"(a[3]), "r"(b[0]), "r"(b[1]));
}

__global__ void __launch_bounds__(512, 2) gemm_k(float* __restrict__ S) {
    __shared__ unsigned Ah[2][2048], Bh[2][2048];
    const int tid = threadIdx.x, lane = tid & 31, wid = tid >> 5;
    const int wm = wid & 3, wn = wid >> 2;
    const int bx = blockIdx.x, by = blockIdx.y;
    const unsigned* Agh = g_Ahp + (size_t)(by << 7) * 256;
    const unsigned* Bgh = g_Bhp + (size_t)(bx << 7) * 256;
    const int lrow = tid >> 2, lk = (tid & 3) << 2;
    const int s_mb = lrow >> 4, s_nb = lrow >> 3;
    const int s_kb = lk >> 3, s_fbit = (lk >> 2) & 1, s_mbit = (lrow >> 3) & 1;
    const size_t goff = (size_t)lrow * 256 + lk;
    const int fragX = (s_fbit << 1) | (s_mbit ^ s_kb);

    uint4 pah = *(const uint4*)(Agh + goff);
    uint4 pbh = *(const uint4*)(Bgh + goff);

    float acc[2][4][4];
#pragma unroll
    for (int i = 0; i < 2; i++)
#pragma unroll
        for (int j = 0; j < 4; j++)
#pragma unroll
            for (int q = 0; q < 4; q++) acc[i][j][q] = 0.f;

#define STORE_STAGE(stg) do {                                               \
    unsigned avh[4] = {pah.x, pah.y, pah.z, pah.w};                         \
    unsigned bvh[4] = {pbh.x, pbh.y, pbh.z, pbh.w};                         \
    _Pragma("unroll")                                                       \
    for (int j = 0; j < 4; j++) {                                           \
        int ls = ((lrow & 7) << 2) | j;                                     \
        int wA = (s_mb * 2 + s_kb) * 128 +                                  \
                 (((ls << 2) | fragX) ^ (((ls >> 3) & 3) << 2));            \
        Ah[stg][wA] = avh[j];                                               \
        int wB = (s_nb * 2 + s_kb) * 64 +                                   \
                 (((ls << 1) | s_fbit) ^ (((ls >> 4) & 1) << 1) ^ (s_kb << 2)); \
        Bh[stg][wB] = bvh[j];                                               \
    } } while (0)

    STORE_STAGE(0);
    __syncthreads();

    const int aoff = (lane << 2) ^ (((lane >> 3) & 3) << 2);
    for (int c = 0; c < 16; c++) {
        int cur = c & 1;
        if (c < 15) {
            size_t g2 = goff + (size_t)(c + 1) * 16;
            pah = *(const uint4*)(Agh + g2);
            pbh = *(const uint4*)(Bgh + g2);
        }
#pragma unroll
        for (int ks = 0; ks < 2; ks++) {
            uint4 ahv[2]; uint2 bhv[4];
#pragma unroll
            for (int mt = 0; mt < 2; mt++) {
                int blk = ((wm * 2 + mt) * 2 + ks) * 128;
                ahv[mt] = *(const uint4*)&Ah[cur][blk + aoff];
            }
            int boff = (lane << 1) ^ (((lane >> 4) & 1) << 1) ^ (ks << 2);
#pragma unroll
            for (int nt = 0; nt < 4; nt++) {
                int blk = ((wn * 4 + nt) * 2 + ks) * 64;
                bhv[nt] = *(const uint2*)&Bh[cur][blk + boff];
            }
            unsigned a_h[2][4];
#pragma unroll
            for (int mt = 0; mt < 2; mt++) {
                if (ks == 0) {
                    a_h[mt][0] = ahv[mt].x; a_h[mt][1] = ahv[mt].y;
                    a_h[mt][2] = ahv[mt].z; a_h[mt][3] = ahv[mt].w;
                } else {   // kb XOR on frag bit0: pair-swapped positions
                    a_h[mt][0] = ahv[mt].y; a_h[mt][1] = ahv[mt].x;
                    a_h[mt][2] = ahv[mt].w; a_h[mt][3] = ahv[mt].z;
                }
            }
#pragma unroll
            for (int mt = 0; mt < 2; mt++)
#pragma unroll
                for (int nt = 0; nt < 4; nt++)
                    mma16(acc[mt][nt], a_h[mt], (const unsigned*)&bhv[nt]);
        }
        if (c < 15) {
            STORE_STAGE(cur ^ 1);
            __syncthreads();
        }
    }
#undef STORE_STAGE
    // epilogue: bf16 store, zero d_out, 12-bit histogram
    __syncthreads();
    int* hsm = (int*)&Ah[0][0];   // 4096 ints = 16KB
    for (int j = tid; j < 4096; j += 512) hsm[j] = 0;
    __syncthreads();
    float2 zz = make_float2(0.f, 0.f);
#pragma unroll
    for (int mt = 0; mt < 2; mt++) {
        int rg = (by << 7) + (wm << 5) + (mt << 4) + (lane >> 2);
#pragma unroll
        for (int nt = 0; nt < 4; nt++) {
            int cg = (bx << 7) + (wn << 5) + (nt << 3) + ((lane & 3) << 1);
            unsigned short b0 = f2bf(acc[mt][nt][0] * 0.25f);
            unsigned short b1 = f2bf(acc[mt][nt][1] * 0.25f);
            unsigned short b2 = f2bf(acc[mt][nt][2] * 0.25f);
            unsigned short b3 = f2bf(acc[mt][nt][3] * 0.25f);
            g_S16[((size_t)rg * N_EDGES + cg) >> 1] = (unsigned)b0 | ((unsigned)b1 << 16);
            g_S16[((size_t)(rg + 8) * N_EDGES + cg) >> 1] = (unsigned)b2 | ((unsigned)b3 << 16);
            *(float2*)(S + (size_t)rg * N_EDGES + cg) = zz;
            *(float2*)(S + (size_t)(rg + 8) * N_EDGES + cg) = zz;
            atomicAdd(&hsm[mkey(bf2f(b0)) >> 20], 1);
            atomicAdd(&hsm[mkey(bf2f(b1)) >> 20], 1);
            atomicAdd(&hsm[mkey(bf2f(b2)) >> 20], 1);
            atomicAdd(&hsm[mkey(bf2f(b3)) >> 20], 1);
        }
    }
    __syncthreads();
    for (int j = tid; j < 4096; j += 512) {
        int v = hsm[j];
        if (v) atomicAdd(&g_h1[j], v);
    }
}

// ---------------- launch 4: mark existing incidences + hist fixup ----------------
__global__ void mask_k(const int* __restrict__ V, const int* __restrict__ E) {
    int i = blockIdx.x * blockDim.x + threadIdx.x;
    if (i >= NNZ) return;
    unsigned idx = (unsigned)V[i] * N_EDGES + (unsigned)E[i];
    unsigned bit = 1u << (idx & 31);
    unsigned old = atomicOr(&g_mbit[idx >> 5], bit);
    if (!(old & bit)) {   // exactly-once per (V,E) duplicate group
        unsigned pr = g_S16[idx >> 1];
        unsigned short hv = (idx & 1) ? (unsigned short)(pr >> 16)
                                      : (unsigned short)(pr & 0xffffu);
        atomicSub(&g_h1[mkey(bf2f(hv)) >> 20], 1);
    }
}

// ---------------- launch 5: pick 12-bit threshold bucket ----------------
__global__ void scan12_k() {
    __shared__ int tot[1024];
    int t = threadIdx.x, base = t * 4;
    int loc[4], s = 0;
#pragma unroll
    for (int j = 0; j < 4; j++) { loc[j] = g_h1[base + j]; s += loc[j]; }
    tot[t] = s; __syncthreads();
    int above = 0;
    for (int u = t + 1; u < 1024; u++) above += tot[u];
    for (int j = 3; j >= 0; j--) {
        int v = loc[j];
        if (above < KSEL && above + v >= KSEL) {
            unsigned klo = (unsigned)(base + j) << 20;
            g_tlo = key2f(klo) - 2.5e-3f;   // hi-only (1e-3) + bf16-S rounding + slack
            g_thi = key2f(klo + 0x100000u) + 2.5e-3f;
        }
        above += v;
    }
}

// ---------------- launch 6: classify candidates (read-only sweep) ----------------
__global__ void collect_k() {
    float tlo = g_tlo, thi = g_thi;
    int i = blockIdx.x * blockDim.x + threadIdx.x, st = gridDim.x * blockDim.x;
    for (; i < NTOT / 8; i += st) {
        uint4 pv = ((const uint4*)g_S16)[i];
        unsigned pw[4] = {pv.x, pv.y, pv.z, pv.w};
#pragma unroll
        for (int j = 0; j < 8; j++) {
            unsigned short hv = (j & 1) ? (unsigned short)(pw[j >> 1] >> 16)
                                        : (unsigned short)(pw[j >> 1] & 0xffffu);
            float f = bf2f(hv);
            if (f > tlo) {
                unsigned idx = (unsigned)(i * 8 + j);
                if (g_mbit[idx >> 5] & (1u << (idx & 31))) continue;  // masked
                if (f > thi) {
                    int p = atomicAdd(&g_sel_n, 1);
                    if (p < SEL_CAP) g_sel[p] = idx;
                } else {
                    int p = atomicAdd(&g_band_n, 1);
                    if (p < BAND_CAP) g_band[p] = idx;
                }
            }
        }
    }
}

// ---------------- launch 7: fp64 recompute of band entries ----------------
__global__ void exactval_k() {
    int nb = g_band_n; if (nb > BAND_CAP) nb = BAND_CAP;
    int j = blockIdx.x * 8 + (threadIdx.x >> 5);
    if (j >= nb) return;
    int lane = threadIdx.x & 31;
    unsigned idx = g_band[j];
    const float* a = g_A + (size_t)(idx >> 13) * KDIM;
    const float* b = g_B + (size_t)(idx & 8191) * KDIM;
    double s = 0.0;
    for (int t = lane; t < KDIM; t += 32) s += (double)a[t] * (double)b[t];
#pragma unroll
    for (int o = 16; o; o >>= 1) s += __shfl_down_sync(0xffffffffu, s, o);
    if (lane == 0) {
        unsigned long long u = (unsigned long long)__double_as_longlong(s * 0.25);
        g_bkey[j] = (u & 0x8000000000000000ull) ? ~u : (u | 0x8000000000000000ull);
    }
}

// ---------------- launch 8: byte-digit radix select (ties -> lowest index) --------
__global__ void bandsel_k() {
    __shared__ int hist[256];
    __shared__ int s_t, s_n;
    __shared__ unsigned long long s_prefix;
    int nb = g_band_n; if (nb > BAND_CAP) nb = BAND_CAP;
    int nsel = g_sel_n; if (nsel > SEL_CAP) nsel = SEL_CAP;
    int t0 = KSEL - nsel;
    int tid = threadIdx.x;
    if (t0 <= 0) { if (tid == 0) g_sel_n = nsel; return; }
    if (t0 >= nb) {
        for (int j = tid; j < nb; j += 1024) g_sel[nsel + j] = g_band[j];
        if (tid == 0) g_sel_n = nsel + nb;
        return;
    }
    if (tid == 0) { s_t = t0; s_prefix = 0ull; }
    __syncthreads();
    for (int b = 7; b >= 0; b--) {
        for (int j = tid; j < 256; j += 1024) hist[j] = 0;
        __syncthreads();
        unsigned long long pref = s_prefix;
        for (int j = tid; j < nb; j += 1024) {
            unsigned long long k = g_bkey[j];
            bool match = (b == 7) || ((k >> ((b + 1) * 8)) == (pref >> ((b + 1) * 8)));
            if (match) atomicAdd(&hist[(int)((k >> (b * 8)) & 255u)], 1);
        }
        __syncthreads();
        if (tid == 0) {
            int t = s_t, above = 0, d;
            for (d = 255; d > 0; d--) {
                if (above + hist[d] >= t) break;
                above += hist[d];
            }
            s_t = t - above;
            s_prefix = pref | ((unsigned long long)(unsigned)d << (b * 8));
        }
        __syncthreads();
    }
    unsigned long long thr = s_prefix;
    if (tid == 0) s_n = nsel;
    __syncthreads();
    for (int j = tid; j < nb; j += 1024)
        if (g_bkey[j] > thr) { int p = atomicAdd(&s_n, 1); g_sel[p] = g_band[j]; }
    __syncthreads();
    if (tid == 0) {
        int need = s_t;
        while (need > 0) {
            unsigned best = 0xFFFFFFFFu; int bj = -1;
            for (int j = 0; j < nb; j++)
                if (g_bkey[j] == thr && g_band[j] < best) { best = g_band[j]; bj = j; }
            if (bj < 0) break;
            g_sel[s_n++] = best; g_bkey[bj] = 0; need--;
        }
        g_sel_n = s_n;
    }
}

// ---------------- launch 9: threefry mask, merged scatters ----------------
__device__ __forceinline__ unsigned rotl32(unsigned x, int r) {
    return __funnelshift_l(x, x, r);
}
__device__ __forceinline__ unsigned tf_bits(unsigned c0, unsigned c1) {
    const unsigned k0 = 0u, k1 = 42u, k2 = 0u ^ 42u ^ 0x1BD11BDAu;
    unsigned x0 = c0 + k0, x1 = c1 + k1;
#define TR(a) x0 += x1; x1 = rotl32(x1, a); x1 ^= x0;
    TR(13) TR(15) TR(26) TR(6)   x0 += k1; x1 += k2 + 1u;
    TR(17) TR(29) TR(16) TR(24)  x0 += k2; x1 += k0 + 2u;
    TR(13) TR(15) TR(26) TR(6)   x0 += k0; x1 += k1 + 3u;
    TR(17) TR(29) TR(16) TR(24)  x0 += k1; x1 += k2 + 4u;
    TR(13) TR(15) TR(26) TR(6)   x0 += k2; x1 += k0 + 5u;
#undef TR
    return x0 ^ x1;
}
__device__ __forceinline__ float maskval(unsigned idx, float p) {
    unsigned bits = tf_bits(0u, idx);
    float u01 = __uint_as_float((bits >> 9) | 0x3f800000u) - 1.0f;
    const float MINV = 1e-6f, MAXV = (float)(1.0 - 1e-6);
    float u = fmaxf(MINV, u01 * (MAXV - MINV) + MINV);
    float lg = (logf(p) - log1pf(-p) + logf(u) - log1pf(-u)) * 2.0f;
    return 1.0f / (1.0f + expf(-lg));
}
__global__ void scat_k(const int* __restrict__ V, const int* __restrict__ E,
                       const float* __restrict__ P, float* __restrict__ out) {
    int i = blockIdx.x * blockDim.x + threadIdx.x;
    unsigned idx;
    if (i < NNZ) {
        idx = (unsigned)V[i] * N_EDGES + (unsigned)E[i];
    } else {
        int j = i - NNZ;
        if (j >= g_sel_n) return;
        idx = g_sel[j];
    }
    out[idx] = maskval(idx, P[idx]);
}

// ---------------- launch ----------------
extern "C" void kernel_launch(void* const* d_in, const int* in_sizes, int n_in,
                              void* d_out, int out_size) {
    const float* X = (const float*)d_in[0];
    const int*   V = (const int*)d_in[2];
    const int*   E = (const int*)d_in[3];
    const float* P = (const float*)d_in[4];
    const float* W = (const float*)d_in[5];
    float* S = (float*)d_out;

    zero_k<<<2048, 256>>>();                                     // 0
    edgecnt_k<<<NNZ * 32 / 256, 256>>>(X, V, E);                 // 1
    build_k<<<(N_CODES + N_EDGES) * 4 * 32 / 256, 256>>>(X, W);  // 2
    gemm_k<<<dim3(N_EDGES / 128, N_CODES / 128), 512>>>(S);      // 3  <- profiled slot
    mask_k<<<NNZ / 256, 256>>>(V, E);                            // 4
    scan12_k<<<1, 1024>>>();                                     // 5
    collect_k<<<4096, 256>>>();                                  // 6
    exactval_k<<<(BAND_CAP + 7) / 8, 256>>>();                   // 7
    bandsel_k<<<1, 1024>>>();                                    // 8
    scat_k<<<(NNZ + SEL_CAP + 255) / 256, 256>>>(V, E, P, S);    // 9
}

// round 17
// speedup vs baseline: 1.1041x; 1.0820x over previous
#include <cuda_runtime.h>

#define N_CODES 4096
#define N_EDGES 8192
#define EMB     128
#define KDIM    512
#define NNZ     65536
#define NTOT    33554432
#define KSEL    6553
#define BAND_CAP 24576
#define SEL_CAP  8192

__device__ float    g_eX[N_EDGES * EMB];
__device__ int      g_icnt[N_EDGES];
__device__ float    g_A[N_CODES * KDIM];
__device__ float    g_B[N_EDGES * KDIM];
// bf16 hi operand buffers, pair-major (uint = bf16x2, 2 K-elems)
__device__ unsigned g_Ahp[N_CODES * 256];
__device__ unsigned g_Bhp[N_EDGES * 256];
__device__ unsigned g_S16[NTOT / 2];        // S matrix, packed bf16 pairs
__device__ unsigned g_mbit[NTOT / 32];      // mask bitmap (existing incidences)
__device__ int      g_h1[4096];
__device__ unsigned g_sel[SEL_CAP];
__device__ unsigned g_band[BAND_CAP];
__device__ unsigned long long g_bkey[BAND_CAP];
__device__ int      g_sel_n, g_band_n;
__device__ float    g_tlo, g_thi;

__device__ __forceinline__ unsigned mkey(float f) {
    unsigned u = __float_as_uint(f);
    return (u & 0x80000000u) ? ~u : (u | 0x80000000u);
}
__device__ __forceinline__ float key2f(unsigned k) {
    unsigned u = (k & 0x80000000u) ? (k ^ 0x80000000u) : ~k;
    return __uint_as_float(u);
}
__device__ __forceinline__ unsigned short f2bf(float x) {
    unsigned u = __float_as_uint(x);
    return (unsigned short)((u + 0x7fffu + ((u >> 16) & 1u)) >> 16);
}
__device__ __forceinline__ float bf2f(unsigned short h) {
    return __uint_as_float(((unsigned)h) << 16);
}

// ---------------- launch 0: zero scratch ----------------
__global__ void zero_k() {
    int i = blockIdx.x * blockDim.x + threadIdx.x, st = gridDim.x * blockDim.x;
    for (int j = i; j < 4096; j += st) g_h1[j] = 0;
    for (int j = i; j < NTOT / 32; j += st) g_mbit[j] = 0;
    for (int j = i; j < N_EDGES * EMB; j += st) g_eX[j] = 0.f;
    for (int j = i; j < N_EDGES; j += st) g_icnt[j] = 0;
    if (i == 0) { g_sel_n = 0; g_band_n = 0; }
}

// ---------------- launch 1: fused edge counts + sums ----------------
__global__ void edgecnt_k(const float* __restrict__ X, const int* __restrict__ V,
                          const int* __restrict__ E) {
    int i = blockIdx.x * blockDim.x + threadIdx.x;
    int nz = i >> 5, lane = i & 31;
    if (nz >= NNZ) return;
    int e = E[nz];
    if (lane == 0) atomicAdd(&g_icnt[e], 1);
    float4 x = ((const float4*)(X + V[nz] * EMB))[lane];
    float* d = g_eX + e * EMB + lane * 4;
    atomicAdd(d + 0, x.x); atomicAdd(d + 1, x.y);
    atomicAdd(d + 2, x.z); atomicAdd(d + 3, x.w);
}

// ---------------- launch 2: build normalized operands ----------------
__global__ void build_k(const float* __restrict__ X, const float* __restrict__ W) {
    int gw = (blockIdx.x * blockDim.x + threadIdx.x) >> 5, lane = threadIdx.x & 31;
    if (gw >= (N_CODES + N_EDGES) * 4) return;
    int h = gw & 3, r = gw >> 2;
    float4 wv = ((const float4*)(W + h * EMB))[lane];
    float4 t;
    if (r < N_CODES) {
        float4 x = ((const float4*)(X + r * EMB))[lane];
        t.x = x.x * wv.x; t.y = x.y * wv.y; t.z = x.z * wv.z; t.w = x.w * wv.w;
    } else {
        int m = r - N_CODES;
        float inv = 1.0f / fmaxf((float)g_icnt[m], 1.0f);
        float4 s = ((const float4*)(g_eX + m * EMB))[lane];
        t.x = s.x * inv * wv.x; t.y = s.y * inv * wv.y;
        t.z = s.z * inv * wv.z; t.w = s.w * inv * wv.w;
    }
    float ss = t.x * t.x + t.y * t.y + t.z * t.z + t.w * t.w;
#pragma unroll
    for (int o = 16; o; o >>= 1) ss += __shfl_xor_sync(0xffffffffu, ss, o);
    float dn = 1.0f / fmaxf(sqrtf(ss), 1e-6f);
    float4 ov = make_float4(t.x * dn, t.y * dn, t.z * dn, t.w * dn);
    bool isA = (r < N_CODES);
    int rl = isA ? r : (r - N_CODES);
    float* dst = isA ? (g_A + (size_t)rl * KDIM + h * EMB)
                     : (g_B + (size_t)rl * KDIM + h * EMB);
    ((float4*)dst)[lane] = ov;
    unsigned short h0 = f2bf(ov.x), h1 = f2bf(ov.y), h2 = f2bf(ov.z), h3 = f2bf(ov.w);
    uint2 hv = make_uint2((unsigned)h0 | ((unsigned)h1 << 16),
                          (unsigned)h2 | ((unsigned)h3 << 16));
    size_t po = (size_t)rl * 256 + h * 64 + lane * 2;
    *(uint2*)((isA ? g_Ahp : g_Bhp) + po) = hv;
}

// ---------------- launch 3: bf16 smem GEMM (256x128 tile) + hist + zero -----------
__device__ __forceinline__ void mma16(float* d, const unsigned* a, const unsigned* b) {
    asm volatile("mma.sync.aligned.m16n8k16.row.col.f32.bf16.bf16.f32 "
        "{%0,%1,%2,%3}, {%4,%5,%6,%7}, {%8,%9}, {%0,%1,%2,%3};\n"
        : "+f"(d[0]), "+f"(d[1]), "+f"(d[2]), "+f"(d[3])
        : "r"(a[0]), "r"(a[1]), "r"(a[2]), "r"(a[3]), "r"(b[0]), "r"(b[1]));
}

__global__ void __launch_bounds__(512, 1) gemm_k(float* __restrict__ S) {
    __shared__ unsigned Ah[2][4096], Bh[2][2048];
    const int tid = threadIdx.x, lane = tid & 31, wid = tid >> 5;
    const int wm = wid & 3, wn = wid >> 2;
    const int bx = blockIdx.x, by = blockIdx.y;
    const unsigned* Agh = g_Ahp + (size_t)(by << 8) * 256;
    const unsigned* Bgh = g_Bhp + (size_t)(bx << 7) * 256;
    const int lrow = tid >> 2, lk = (tid & 3) << 2;
    const int s_mb = lrow >> 4, s_nb = lrow >> 3;
    const int s_kb = lk >> 3, s_fbit = (lk >> 2) & 1, s_mbit = (lrow >> 3) & 1;
    const size_t goff = (size_t)lrow * 256 + lk;
    const int fragX = (s_fbit << 1) | (s_mbit ^ s_kb);

    uint4 pah0 = *(const uint4*)(Agh + goff);
    uint4 pah1 = *(const uint4*)(Agh + goff + (size_t)128 * 256);
    uint4 pbh  = *(const uint4*)(Bgh + goff);

    float acc[4][4][4];
#pragma unroll
    for (int i = 0; i < 4; i++)
#pragma unroll
        for (int j = 0; j < 4; j++)
#pragma unroll
            for (int q = 0; q < 4; q++) acc[i][j][q] = 0.f;

#define STORE_STAGE(stg) do {                                               \
    unsigned a0[4] = {pah0.x, pah0.y, pah0.z, pah0.w};                      \
    unsigned a1[4] = {pah1.x, pah1.y, pah1.z, pah1.w};                      \
    unsigned bv[4] = {pbh.x, pbh.y, pbh.z, pbh.w};                          \
    _Pragma("unroll")                                                       \
    for (int j = 0; j < 4; j++) {                                           \
        int ls = ((lrow & 7) << 2) | j;                                     \
        int wA = (s_mb * 2 + s_kb) * 128 +                                  \
                 (((ls << 2) | fragX) ^ (((ls >> 3) & 3) << 2));            \
        Ah[stg][wA] = a0[j];                                                \
        Ah[stg][wA + 2048] = a1[j];   /* row+128 -> s_mb+8 */               \
        int wB = (s_nb * 2 + s_kb) * 64 +                                   \
                 (((ls << 1) | s_fbit) ^ (((ls >> 4) & 1) << 1) ^ (s_kb << 2)); \
        Bh[stg][wB] = bv[j];                                                \
    } } while (0)

    STORE_STAGE(0);
    __syncthreads();

    const int aoff = (lane << 2) ^ (((lane >> 3) & 3) << 2);
    for (int c = 0; c < 16; c++) {
        int cur = c & 1;
        if (c < 15) {
            size_t g2 = goff + (size_t)(c + 1) * 16;
            pah0 = *(const uint4*)(Agh + g2);
            pah1 = *(const uint4*)(Agh + g2 + (size_t)128 * 256);
            pbh  = *(const uint4*)(Bgh + g2);
        }
#pragma unroll
        for (int ks = 0; ks < 2; ks++) {
            uint4 ahv[4]; uint2 bhv[4];
#pragma unroll
            for (int mt = 0; mt < 4; mt++) {
                int blk = ((wm * 4 + mt) * 2 + ks) * 128;
                ahv[mt] = *(const uint4*)&Ah[cur][blk + aoff];
            }
            int boff = (lane << 1) ^ (((lane >> 4) & 1) << 1) ^ (ks << 2);
#pragma unroll
            for (int nt = 0; nt < 4; nt++) {
                int blk = ((wn * 4 + nt) * 2 + ks) * 64;
                bhv[nt] = *(const uint2*)&Bh[cur][blk + boff];
            }
            unsigned a_h[4][4];
#pragma unroll
            for (int mt = 0; mt < 4; mt++) {
                if (ks == 0) {
                    a_h[mt][0] = ahv[mt].x; a_h[mt][1] = ahv[mt].y;
                    a_h[mt][2] = ahv[mt].z; a_h[mt][3] = ahv[mt].w;
                } else {   // kb XOR on frag bit0: pair-swapped positions
                    a_h[mt][0] = ahv[mt].y; a_h[mt][1] = ahv[mt].x;
                    a_h[mt][2] = ahv[mt].w; a_h[mt][3] = ahv[mt].z;
                }
            }
#pragma unroll
            for (int mt = 0; mt < 4; mt++)
#pragma unroll
                for (int nt = 0; nt < 4; nt++)
                    mma16(acc[mt][nt], a_h[mt], (const unsigned*)&bhv[nt]);
        }
        if (c < 15) {
            STORE_STAGE(cur ^ 1);
            __syncthreads();
        }
    }
#undef STORE_STAGE
    // epilogue: bf16 store, zero d_out, 12-bit histogram
    __syncthreads();
    int* hsm = (int*)&Ah[0][0];   // 4096 ints = 16KB
    for (int j = tid; j < 4096; j += 512) hsm[j] = 0;
    __syncthreads();
    float2 zz = make_float2(0.f, 0.f);
#pragma unroll
    for (int mt = 0; mt < 4; mt++) {
        int rg = (by << 8) + (wm << 6) + (mt << 4) + (lane >> 2);
#pragma unroll
        for (int nt = 0; nt < 4; nt++) {
            int cg = (bx << 7) + (wn << 5) + (nt << 3) + ((lane & 3) << 1);
            unsigned short b0 = f2bf(acc[mt][nt][0] * 0.25f);
            unsigned short b1 = f2bf(acc[mt][nt][1] * 0.25f);
            unsigned short b2 = f2bf(acc[mt][nt][2] * 0.25f);
            unsigned short b3 = f2bf(acc[mt][nt][3] * 0.25f);
            g_S16[((size_t)rg * N_EDGES + cg) >> 1] = (unsigned)b0 | ((unsigned)b1 << 16);
            g_S16[((size_t)(rg + 8) * N_EDGES + cg) >> 1] = (unsigned)b2 | ((unsigned)b3 << 16);
            *(float2*)(S + (size_t)rg * N_EDGES + cg) = zz;
            *(float2*)(S + (size_t)(rg + 8) * N_EDGES + cg) = zz;
            atomicAdd(&hsm[mkey(bf2f(b0)) >> 20], 1);
            atomicAdd(&hsm[mkey(bf2f(b1)) >> 20], 1);
            atomicAdd(&hsm[mkey(bf2f(b2)) >> 20], 1);
            atomicAdd(&hsm[mkey(bf2f(b3)) >> 20], 1);
        }
    }
    __syncthreads();
    for (int j = tid; j < 4096; j += 512) {
        int v = hsm[j];
        if (v) atomicAdd(&g_h1[j], v);
    }
}

// ---------------- launch 4: mark existing incidences + hist fixup ----------------
__global__ void mask_k(const int* __restrict__ V, const int* __restrict__ E) {
    int i = blockIdx.x * blockDim.x + threadIdx.x;
    if (i >= NNZ) return;
    unsigned idx = (unsigned)V[i] * N_EDGES + (unsigned)E[i];
    unsigned bit = 1u << (idx & 31);
    unsigned old = atomicOr(&g_mbit[idx >> 5], bit);
    if (!(old & bit)) {   // exactly-once per (V,E) duplicate group
        unsigned pr = g_S16[idx >> 1];
        unsigned short hv = (idx & 1) ? (unsigned short)(pr >> 16)
                                      : (unsigned short)(pr & 0xffffu);
        atomicSub(&g_h1[mkey(bf2f(hv)) >> 20], 1);
    }
}

// ---------------- launch 5: pick 12-bit threshold bucket ----------------
__global__ void scan12_k() {
    __shared__ int tot[1024];
    int t = threadIdx.x, base = t * 4;
    int loc[4], s = 0;
#pragma unroll
    for (int j = 0; j < 4; j++) { loc[j] = g_h1[base + j]; s += loc[j]; }
    tot[t] = s; __syncthreads();
    int above = 0;
    for (int u = t + 1; u < 1024; u++) above += tot[u];
    for (int j = 3; j >= 0; j--) {
        int v = loc[j];
        if (above < KSEL && above + v >= KSEL) {
            unsigned klo = (unsigned)(base + j) << 20;
            g_tlo = key2f(klo) - 2.5e-3f;   // hi-only (1e-3) + bf16-S rounding + slack
            g_thi = key2f(klo + 0x100000u) + 2.5e-3f;
        }
        above += v;
    }
}

// ---------------- launch 6: classify candidates (read-only sweep) ----------------
__global__ void collect_k() {
    float tlo = g_tlo, thi = g_thi;
    int i = blockIdx.x * blockDim.x + threadIdx.x, st = gridDim.x * blockDim.x;
    for (; i < NTOT / 8; i += st) {
        uint4 pv = ((const uint4*)g_S16)[i];
        unsigned pw[4] = {pv.x, pv.y, pv.z, pv.w};
#pragma unroll
        for (int j = 0; j < 8; j++) {
            unsigned short hv = (j & 1) ? (unsigned short)(pw[j >> 1] >> 16)
                                        : (unsigned short)(pw[j >> 1] & 0xffffu);
            float f = bf2f(hv);
            if (f > tlo) {
                unsigned idx = (unsigned)(i * 8 + j);
                if (g_mbit[idx >> 5] & (1u << (idx & 31))) continue;  // masked
                if (f > thi) {
                    int p = atomicAdd(&g_sel_n, 1);
                    if (p < SEL_CAP) g_sel[p] = idx;
                } else {
                    int p = atomicAdd(&g_band_n, 1);
                    if (p < BAND_CAP) g_band[p] = idx;
                }
            }
        }
    }
}

// ---------------- launch 7: fp64 recompute of band entries ----------------
__global__ void exactval_k() {
    int nb = g_band_n; if (nb > BAND_CAP) nb = BAND_CAP;
    int j = blockIdx.x * 8 + (threadIdx.x >> 5);
    if (j >= nb) return;
    int lane = threadIdx.x & 31;
    unsigned idx = g_band[j];
    const float* a = g_A + (size_t)(idx >> 13) * KDIM;
    const float* b = g_B + (size_t)(idx & 8191) * KDIM;
    double s = 0.0;
    for (int t = lane; t < KDIM; t += 32) s += (double)a[t] * (double)b[t];
#pragma unroll
    for (int o = 16; o; o >>= 1) s += __shfl_down_sync(0xffffffffu, s, o);
    if (lane == 0) {
        unsigned long long u = (unsigned long long)__double_as_longlong(s * 0.25);
        g_bkey[j] = (u & 0x8000000000000000ull) ? ~u : (u | 0x8000000000000000ull);
    }
}

// ---------------- launch 8: byte-digit radix select (ties -> lowest index) --------
__global__ void bandsel_k() {
    __shared__ int hist[256];
    __shared__ int s_t, s_n;
    __shared__ unsigned long long s_prefix;
    int nb = g_band_n; if (nb > BAND_CAP) nb = BAND_CAP;
    int nsel = g_sel_n; if (nsel > SEL_CAP) nsel = SEL_CAP;
    int t0 = KSEL - nsel;
    int tid = threadIdx.x;
    if (t0 <= 0) { if (tid == 0) g_sel_n = nsel; return; }
    if (t0 >= nb) {
        for (int j = tid; j < nb; j += 1024) g_sel[nsel + j] = g_band[j];
        if (tid == 0) g_sel_n = nsel + nb;
        return;
    }
    if (tid == 0) { s_t = t0; s_prefix = 0ull; }
    __syncthreads();
    for (int b = 7; b >= 0; b--) {
        for (int j = tid; j < 256; j += 1024) hist[j] = 0;
        __syncthreads();
        unsigned long long pref = s_prefix;
        for (int j = tid; j < nb; j += 1024) {
            unsigned long long k = g_bkey[j];
            bool match = (b == 7) || ((k >> ((b + 1) * 8)) == (pref >> ((b + 1) * 8)));
            if (match) atomicAdd(&hist[(int)((k >> (b * 8)) & 255u)], 1);
        }
        __syncthreads();
        if (tid == 0) {
            int t = s_t, above = 0, d;
            for (d = 255; d > 0; d--) {
                if (above + hist[d] >= t) break;
                above += hist[d];
            }
            s_t = t - above;
            s_prefix = pref | ((unsigned long long)(unsigned)d << (b * 8));
        }
        __syncthreads();
    }
    unsigned long long thr = s_prefix;
    if (tid == 0) s_n = nsel;
    __syncthreads();
    for (int j = tid; j < nb; j += 1024)
        if (g_bkey[j] > thr) { int p = atomicAdd(&s_n, 1); g_sel[p] = g_band[j]; }
    __syncthreads();
    if (tid == 0) {
        int need = s_t;
        while (need > 0) {
            unsigned best = 0xFFFFFFFFu; int bj = -1;
            for (int j = 0; j < nb; j++)
                if (g_bkey[j] == thr && g_band[j] < best) { best = g_band[j]; bj = j; }
            if (bj < 0) break;
            g_sel[s_n++] = best; g_bkey[bj] = 0; need--;
        }
        g_sel_n = s_n;
    }
}

// ---------------- launch 9: threefry mask, merged scatters ----------------
__device__ __forceinline__ unsigned rotl32(unsigned x, int r) {
    return __funnelshift_l(x, x, r);
}
__device__ __forceinline__ unsigned tf_bits(unsigned c0, unsigned c1) {
    const unsigned k0 = 0u, k1 = 42u, k2 = 0u ^ 42u ^ 0x1BD11BDAu;
    unsigned x0 = c0 + k0, x1 = c1 + k1;
#define TR(a) x0 += x1; x1 = rotl32(x1, a); x1 ^= x0;
    TR(13) TR(15) TR(26) TR(6)   x0 += k1; x1 += k2 + 1u;
    TR(17) TR(29) TR(16) TR(24)  x0 += k2; x1 += k0 + 2u;
    TR(13) TR(15) TR(26) TR(6)   x0 += k0; x1 += k1 + 3u;
    TR(17) TR(29) TR(16) TR(24)  x0 += k1; x1 += k2 + 4u;
    TR(13) TR(15) TR(26) TR(6)   x0 += k2; x1 += k0 + 5u;
#undef TR
    return x0 ^ x1;
}
__device__ __forceinline__ float maskval(unsigned idx, float p) {
    unsigned bits = tf_bits(0u, idx);
    float u01 = __uint_as_float((bits >> 9) | 0x3f800000u) - 1.0f;
    const float MINV = 1e-6f, MAXV = (float)(1.0 - 1e-6);
    float u = fmaxf(MINV, u01 * (MAXV - MINV) + MINV);
    float lg = (logf(p) - log1pf(-p) + logf(u) - log1pf(-u)) * 2.0f;
    return 1.0f / (1.0f + expf(-lg));
}
__global__ void scat_k(const int* __restrict__ V, const int* __restrict__ E,
                       const float* __restrict__ P, float* __restrict__ out) {
    int i = blockIdx.x * blockDim.x + threadIdx.x;
    unsigned idx;
    if (i < NNZ) {
        idx = (unsigned)V[i] * N_EDGES + (unsigned)E[i];
    } else {
        int j = i - NNZ;
        if (j >= g_sel_n) return;
        idx = g_sel[j];
    }
    out[idx] = maskval(idx, P[idx]);
}

// ---------------- launch ----------------
extern "C" void kernel_launch(void* const* d_in, const int* in_sizes, int n_in,
                              void* d_out, int out_size) {
    const float* X = (const float*)d_in[0];
    const int*   V = (const int*)d_in[2];
    const int*   E = (const int*)d_in[3];
    const float* P = (const float*)d_in[4];
    const float* W = (const float*)d_in[5];
    float* S = (float*)d_out;

    zero_k<<<2048, 256>>>();                                     // 0
    edgecnt_k<<<NNZ * 32 / 256, 256>>>(X, V, E);                 // 1
    build_k<<<(N_CODES + N_EDGES) * 4 * 32 / 256, 256>>>(X, W);  // 2
    gemm_k<<<dim3(N_EDGES / 128, N_CODES / 256), 512>>>(S);      // 3  <- profiled slot
    mask_k<<<NNZ / 256, 256>>>(V, E);                            // 4
    scan12_k<<<1, 1024>>>();                                     // 5
    collect_k<<<4096, 256>>>();                                  // 6
    exactval_k<<<(BAND_CAP + 7) / 8, 256>>>();                   // 7
    bandsel_k<<<1, 1024>>>();                                    // 8
    scat_k<<<(NNZ + SEL_CAP + 255) / 256, 256>>>(V, E, P, S);    // 9
}